// round 2
// baseline (speedup 1.0000x reference)
#include <cuda_runtime.h>

#define N_NODES 100000
#define F 64
#define N_EDGES 500000
#define NCH 9
#define NEG 0.2f
#define TILE 128
#define NT ((N_NODES + TILE - 1) / TILE)   // 782

typedef unsigned long long ull;

// ---------------- scratch (device globals; no allocations allowed) ----------
__device__ float g_h1[(size_t)NCH * N_NODES * F];
__device__ float g_agg[(size_t)NCH * N_NODES * F];
__device__ float g_h2[(size_t)NCH * N_NODES * F];
__device__ float g_x2[(size_t)NCH * N_NODES * F];
__device__ float g_den1[NCH * N_NODES];
__device__ float g_den2[NCH * N_NODES];
__device__ float g_ss1[NCH * N_NODES];
__device__ float g_sd1[NCH * N_NODES];
__device__ float g_ss2[NCH * N_NODES];
__device__ float g_sd2[NCH * N_NODES];

// ---------------- f32x2 helpers ----------------
__device__ __forceinline__ ull fma2(ull a, ull b, ull c) {
    ull d;
    asm("fma.rn.f32x2 %0, %1, %2, %3;" : "=l"(d) : "l"(a), "l"(b), "l"(c));
    return d;
}
__device__ __forceinline__ ull dup2(float x) {
    ull r;
    asm("mov.b64 %0, {%1, %1};" : "=l"(r) : "f"(x));
    return r;
}
__device__ __forceinline__ void unpack2(ull v, float& lo, float& hi) {
    asm("mov.b64 {%0, %1}, %2;" : "=f"(lo), "=f"(hi) : "l"(v));
}

// ---------------- fused GEMM + scores + self-loop init, all channels --------
// Per (channel, 128-row tile) block:
//   h = X @ W ; ps = h@a_src ; pd = h@a_dst ; w = exp(leaky(ps+pd))
//   agg = w*h (self-loop seed) ; den = w
// layer==1: X = relu(g_agg/g_den1 + b1) computed on the fly.
__global__ __launch_bounds__(256, 2) void gat_gemm_all(
    const float* __restrict__ Xg,
    const float* __restrict__ Wall,
    const float* __restrict__ asall,
    const float* __restrict__ adall,
    const float* __restrict__ bprevall,
    int layer)
{
    extern __shared__ char smem[];
    ull*   Wd  = (ull*)smem;                         // [64][64] dup'd W  (32KB)
    ull*   Xt  = (ull*)(smem + 32768);               // [64][66] k-major row pairs (33.8KB)
    float* ash = (float*)(smem + 32768 + 64 * 66 * 8);
    float* adsh = ash + F;
    float* bsh  = adsh + F;

    const int bx = blockIdx.x;
    const int c = bx / NT;
    const int tile = bx % NT;
    const int tid = threadIdx.x;
    const int rowbase = tile * TILE;

    // ---- load W (dup'd) and vectors ----
    const float* W = Wall + (size_t)c * F * F;
    for (int i = tid; i < F * F; i += 256)
        Wd[i] = dup2(W[i]);                          // i = k*64 + col
    if (tid < F) {
        ash[tid]  = asall[c * F + tid];
        adsh[tid] = adall[c * F + tid];
        bsh[tid]  = layer ? bprevall[c * F + tid] : 0.f;
    }
    __syncthreads();

    const float* aggin = g_agg + (size_t)c * N_NODES * F;
    const float* denin = g_den1 + (size_t)c * N_NODES;
    float* hout   = (layer ? g_h2 : g_h1) + (size_t)c * N_NODES * F;
    float* aggout = (layer ? g_x2 : g_agg) + (size_t)c * N_NODES * F;
    float* denout = (layer ? g_den2 : g_den1) + (size_t)c * N_NODES;
    float* ssout  = (layer ? g_ss2 : g_ss1) + (size_t)c * N_NODES;
    float* sdout  = (layer ? g_sd2 : g_sd1) + (size_t)c * N_NODES;

    // ---- fill Xt (transpose to k-major; conflict-free STS) ----
    float* xtf = (float*)Xt;                          // float index: k*132 + row
    #pragma unroll
    for (int it = 0; it < 8; it++) {
        int lin = it * 256 + tid;
        int kg = lin >> 7;          // 0..15 (4 k's each)
        int row = lin & 127;
        int gr = rowbase + row;
        float4 v = make_float4(0.f, 0.f, 0.f, 0.f);
        if (gr < N_NODES) {
            if (layer == 0) {
                v = *(const float4*)&Xg[(size_t)gr * F + 4 * kg];
            } else {
                float4 a = *(const float4*)&aggin[(size_t)gr * F + 4 * kg];
                float inv = 1.f / denin[gr];
                v.x = fmaxf(fmaf(a.x, inv, bsh[4 * kg + 0]), 0.f);
                v.y = fmaxf(fmaf(a.y, inv, bsh[4 * kg + 1]), 0.f);
                v.z = fmaxf(fmaf(a.z, inv, bsh[4 * kg + 2]), 0.f);
                v.w = fmaxf(fmaf(a.w, inv, bsh[4 * kg + 3]), 0.f);
            }
        }
        int base = 4 * kg * 132 + row;
        xtf[base]       = v.x;
        xtf[base + 132] = v.y;
        xtf[base + 264] = v.z;
        xtf[base + 396] = v.w;
    }
    __syncthreads();

    // ---- mainloop: acc[rp][cc] over k ----
    const int tx = tid & 15;     // col group: cols 4tx..4tx+3
    const int ty = tid >> 4;     // row group: rows 8ty..8ty+7 (pairs 4ty..4ty+3)
    ull acc[4][4];
    #pragma unroll
    for (int i = 0; i < 4; i++)
        #pragma unroll
        for (int j = 0; j < 4; j++) acc[i][j] = 0ull;

    #pragma unroll 4
    for (int k = 0; k < F; k++) {
        ulonglong2 w01 = *(const ulonglong2*)&Wd[k * 64 + 4 * tx];
        ulonglong2 w23 = *(const ulonglong2*)&Wd[k * 64 + 4 * tx + 2];
        ulonglong2 x01 = *(const ulonglong2*)&Xt[k * 66 + 4 * ty];
        ulonglong2 x23 = *(const ulonglong2*)&Xt[k * 66 + 4 * ty + 2];
        acc[0][0] = fma2(x01.x, w01.x, acc[0][0]);
        acc[0][1] = fma2(x01.x, w01.y, acc[0][1]);
        acc[0][2] = fma2(x01.x, w23.x, acc[0][2]);
        acc[0][3] = fma2(x01.x, w23.y, acc[0][3]);
        acc[1][0] = fma2(x01.y, w01.x, acc[1][0]);
        acc[1][1] = fma2(x01.y, w01.y, acc[1][1]);
        acc[1][2] = fma2(x01.y, w23.x, acc[1][2]);
        acc[1][3] = fma2(x01.y, w23.y, acc[1][3]);
        acc[2][0] = fma2(x23.x, w01.x, acc[2][0]);
        acc[2][1] = fma2(x23.x, w01.y, acc[2][1]);
        acc[2][2] = fma2(x23.x, w23.x, acc[2][2]);
        acc[2][3] = fma2(x23.x, w23.y, acc[2][3]);
        acc[3][0] = fma2(x23.y, w01.x, acc[3][0]);
        acc[3][1] = fma2(x23.y, w01.y, acc[3][1]);
        acc[3][2] = fma2(x23.y, w23.x, acc[3][2]);
        acc[3][3] = fma2(x23.y, w23.y, acc[3][3]);
    }

    // ---- epilogue: scores, softmax seed, stores ----
    float hr[8][4];
    #pragma unroll
    for (int rp = 0; rp < 4; rp++)
        #pragma unroll
        for (int cc = 0; cc < 4; cc++)
            unpack2(acc[rp][cc], hr[2 * rp][cc], hr[2 * rp + 1][cc]);

    float a0 = ash[4 * tx], a1 = ash[4 * tx + 1], a2 = ash[4 * tx + 2], a3 = ash[4 * tx + 3];
    float d0 = adsh[4 * tx], d1 = adsh[4 * tx + 1], d2 = adsh[4 * tx + 2], d3 = adsh[4 * tx + 3];

    float ps[8], pd[8];
    #pragma unroll
    for (int r = 0; r < 8; r++) {
        ps[r] = hr[r][0] * a0 + hr[r][1] * a1 + hr[r][2] * a2 + hr[r][3] * a3;
        pd[r] = hr[r][0] * d0 + hr[r][1] * d1 + hr[r][2] * d2 + hr[r][3] * d3;
    }
    #pragma unroll
    for (int off = 1; off < 16; off <<= 1) {
        #pragma unroll
        for (int r = 0; r < 8; r++) {
            ps[r] += __shfl_xor_sync(0xffffffffu, ps[r], off);
            pd[r] += __shfl_xor_sync(0xffffffffu, pd[r], off);
        }
    }

    #pragma unroll
    for (int r = 0; r < 8; r++) {
        int grow = rowbase + 8 * ty + r;
        if (grow < N_NODES) {
            float e = ps[r] + pd[r];
            e = e > 0.f ? e : NEG * e;
            float w = __expf(e);
            float4 hv = make_float4(hr[r][0], hr[r][1], hr[r][2], hr[r][3]);
            *(float4*)&hout[(size_t)grow * F + 4 * tx] = hv;
            *(float4*)&aggout[(size_t)grow * F + 4 * tx] =
                make_float4(w * hv.x, w * hv.y, w * hv.z, w * hv.w);
            if (tx == 0) {
                ssout[grow] = ps[r];
                sdout[grow] = pd[r];
                denout[grow] = w;
            }
        }
    }
}

// ---------------- edge scatter, all channels ----------------
__global__ __launch_bounds__(256) void gat_edge_all(const int* __restrict__ EI, int layer)
{
    int gid = blockIdx.x * 256 + threadIdx.x;
    int eg = gid >> 4;
    int j = gid & 15;
    int c = eg / N_EDGES;
    int e = eg - c * N_EDGES;

    const int* src = EI + ((size_t)(c * 2 + layer) * 2) * N_EDGES;
    const int* dst = src + N_EDGES;

    const float* h;
    const float* ss;
    const float* sd;
    float* agg;
    float* den;
    if (layer == 0) { h = g_h1; ss = g_ss1; sd = g_sd1; agg = g_agg; den = g_den1; }
    else            { h = g_h2; ss = g_ss2; sd = g_sd2; agg = g_x2;  den = g_den2; }
    h   += (size_t)c * N_NODES * F;
    agg += (size_t)c * N_NODES * F;
    ss  += (size_t)c * N_NODES;
    sd  += (size_t)c * N_NODES;
    den += (size_t)c * N_NODES;

    int s = __ldg(&src[e]);
    int d = __ldg(&dst[e]);
    float ev = ss[s] + sd[d];
    ev = ev > 0.f ? ev : NEG * ev;
    float w = __expf(ev);

    float4 hv = *(const float4*)&h[(size_t)s * F + 4 * j];
    float* p = &agg[(size_t)d * F + 4 * j];
    asm volatile("red.global.add.v4.f32 [%0], {%1,%2,%3,%4};"
                 :: "l"(p), "f"(w * hv.x), "f"(w * hv.y), "f"(w * hv.z), "f"(w * hv.w)
                 : "memory");
    if (j == 0) atomicAdd(&den[d], w);
}

// ---------------- channel attention combine ----------------
__global__ __launch_bounds__(256) void gat_final(
    const float* __restrict__ b2, const float* __restrict__ att, float* __restrict__ out)
{
    __shared__ float attsh[NCH * F];
    __shared__ float b2sh[NCH * F];
    for (int i = threadIdx.x; i < NCH * F; i += 256) { attsh[i] = att[i]; b2sh[i] = b2[i]; }
    __syncthreads();

    int tid = blockIdx.x * 256 + threadIdx.x;
    int node = tid >> 4;
    int j = tid & 15;
    if (node >= N_NODES) return;

    float4 xs[NCH];
    float sc[NCH];
    #pragma unroll
    for (int c = 0; c < NCH; c++) {
        float inv = 1.f / g_den2[(size_t)c * N_NODES + node];
        float4 v = *(const float4*)&g_x2[((size_t)c * N_NODES + node) * F + 4 * j];
        int cb = c * F + 4 * j;
        v.x = v.x * inv + b2sh[cb + 0];
        v.y = v.y * inv + b2sh[cb + 1];
        v.z = v.z * inv + b2sh[cb + 2];
        v.w = v.w * inv + b2sh[cb + 3];
        xs[c] = v;
        sc[c] = v.x * attsh[cb + 0] + v.y * attsh[cb + 1] + v.z * attsh[cb + 2] + v.w * attsh[cb + 3];
    }
    #pragma unroll
    for (int off = 1; off < 16; off <<= 1) {
        #pragma unroll
        for (int c = 0; c < NCH; c++) sc[c] += __shfl_xor_sync(0xffffffffu, sc[c], off);
    }
    float mx = sc[0];
    #pragma unroll
    for (int c = 1; c < NCH; c++) mx = fmaxf(mx, sc[c]);
    float sum = 0.f;
    float wch[NCH];
    #pragma unroll
    for (int c = 0; c < NCH; c++) { wch[c] = __expf(sc[c] - mx); sum += wch[c]; }
    float inv = 1.f / sum;
    float4 o = make_float4(0.f, 0.f, 0.f, 0.f);
    #pragma unroll
    for (int c = 0; c < NCH; c++) {
        float a = wch[c] * inv;
        o.x += a * xs[c].x; o.y += a * xs[c].y; o.z += a * xs[c].z; o.w += a * xs[c].w;
    }
    *(float4*)&out[(size_t)node * F + 4 * j] = o;
}

// ---------------- launch ----------------
extern "C" void kernel_launch(void* const* d_in, const int* in_sizes, int n_in,
                              void* d_out, int out_size)
{
    const float* emb = (const float*)d_in[0];
    const float* W1  = (const float*)d_in[1];
    const float* as1 = (const float*)d_in[2];
    const float* ad1 = (const float*)d_in[3];
    const float* b1  = (const float*)d_in[4];
    const float* W2  = (const float*)d_in[5];
    const float* as2 = (const float*)d_in[6];
    const float* ad2 = (const float*)d_in[7];
    const float* b2  = (const float*)d_in[8];
    const float* att = (const float*)d_in[9];
    const int*   EI  = (const int*)d_in[10];
    float* out = (float*)d_out;

    const int smem_bytes = 32768 + 64 * 66 * 8 + 3 * F * 4;  // 67328
    cudaFuncSetAttribute(gat_gemm_all, cudaFuncAttributeMaxDynamicSharedMemorySize, smem_bytes);

    const int gemm_grid = NCH * NT;                        // 7038
    const int edge_grid = (NCH * N_EDGES * 16) / 256;      // 281250 (exact)
    const int fin_grid  = (N_NODES * 16) / 256;            // 6250 (exact)

    gat_gemm_all<<<gemm_grid, 256, smem_bytes>>>(emb, W1, as1, ad1, b1, 0);
    gat_edge_all<<<edge_grid, 256>>>(EI, 0);
    gat_gemm_all<<<gemm_grid, 256, smem_bytes>>>(emb, W2, as2, ad2, b1, 1);
    gat_edge_all<<<edge_grid, 256>>>(EI, 1);
    gat_final<<<fin_grid, 256>>>(b2, att, out);
}

// round 4
// speedup vs baseline: 1.1866x; 1.1866x over previous
#include <cuda_runtime.h>

#define N_NODES 100000
#define F 64
#define N_EDGES 500000
#define NCH 9
#define NEG 0.2f
#define TILE 256
#define NT ((N_NODES + TILE - 1) / TILE)   // 391

typedef unsigned long long ull;

// ---------------- scratch (device globals; no allocations allowed) ----------
__device__ float g_h1[(size_t)NCH * N_NODES * F];
__device__ float g_agg[(size_t)NCH * N_NODES * F];
__device__ float g_h2[(size_t)NCH * N_NODES * F];
__device__ float g_x2[(size_t)NCH * N_NODES * F];
__device__ float g_den1[NCH * N_NODES];
__device__ float g_den2[NCH * N_NODES];
__device__ float g_ss1[NCH * N_NODES];
__device__ float g_sd1[NCH * N_NODES];
__device__ float g_ss2[NCH * N_NODES];
__device__ float g_sd2[NCH * N_NODES];

// ---------------- f32x2 helpers ----------------
__device__ __forceinline__ ull fma2(ull a, ull b, ull c) {
    ull d;
    asm("fma.rn.f32x2 %0, %1, %2, %3;" : "=l"(d) : "l"(a), "l"(b), "l"(c));
    return d;
}
__device__ __forceinline__ ull dup2(float x) {
    ull r;
    asm("mov.b64 %0, {%1, %1};" : "=l"(r) : "f"(x));
    return r;
}
__device__ __forceinline__ void unpack2(ull v, float& lo, float& hi) {
    asm("mov.b64 {%0, %1}, %2;" : "=f"(lo), "=f"(hi) : "l"(v));
}

// ---------------- fused GEMM + scores + self-loop init, all channels --------
// Block: 128 threads, one (channel, 256-row) tile.
// Micro-tile: 16 rows x 8 cols per thread. X in smem k-major as row pairs,
// W in smem k-major scalar (dup'd to f32x2 in registers via ALU-pipe mov).
// layer==1: X = relu(g_agg/g_den1 + b1) computed on the fly.
__global__ __launch_bounds__(128, 2) void gat_gemm_all(
    const float* __restrict__ Xg,
    const float* __restrict__ Wall,
    const float* __restrict__ asall,
    const float* __restrict__ adall,
    const float* __restrict__ bprevall,
    int layer)
{
    extern __shared__ char smem[];
    float* Ws = (float*)smem;                              // [64][64] scalar, 16KB
    ull*   Xt = (ull*)(smem + 16384);                      // [64][130] row-pairs
    float* ash  = (float*)(smem + 16384 + 64 * 130 * 8);
    float* adsh = ash + F;
    float* bsh  = adsh + F;

    const int bx = blockIdx.x;
    const int c = bx / NT;
    const int tile = bx % NT;
    const int tid = threadIdx.x;
    const int rowbase = tile * TILE;

    const float* W = Wall + (size_t)c * F * F;
    for (int i = tid; i < F * F / 4; i += 128)
        ((float4*)Ws)[i] = ((const float4*)W)[i];
    if (tid < F) {
        ash[tid]  = asall[c * F + tid];
        adsh[tid] = adall[c * F + tid];
        bsh[tid]  = layer ? bprevall[c * F + tid] : 0.f;
    }
    __syncthreads();   // bsh is read by the Xt fill below (layer 1) — required

    const float* aggin = g_agg + (size_t)c * N_NODES * F;
    const float* denin = g_den1 + (size_t)c * N_NODES;
    float* hout   = (layer ? g_h2 : g_h1) + (size_t)c * N_NODES * F;
    float* aggout = (layer ? g_x2 : g_agg) + (size_t)c * N_NODES * F;
    float* denout = (layer ? g_den2 : g_den1) + (size_t)c * N_NODES;
    float* ssout  = (layer ? g_ss2 : g_ss1) + (size_t)c * N_NODES;
    float* sdout  = (layer ? g_sd2 : g_sd1) + (size_t)c * N_NODES;

    // ---- fill Xt: transpose 256 rows x 64 cols to k-major (float idx k*260+row)
    float* xtf = (float*)Xt;
    #pragma unroll
    for (int it = 0; it < 32; it++) {
        int lin = it * 128 + tid;          // 0..4095 float4s
        int kg = lin >> 8;                 // 0..15 (4 k each)
        int row = lin & 255;
        int gr = rowbase + row;
        float4 v = make_float4(0.f, 0.f, 0.f, 0.f);
        if (gr < N_NODES) {
            if (layer == 0) {
                v = *(const float4*)&Xg[(size_t)gr * F + 4 * kg];
            } else {
                float4 a = *(const float4*)&aggin[(size_t)gr * F + 4 * kg];
                float inv = 1.f / denin[gr];
                v.x = fmaxf(fmaf(a.x, inv, bsh[4 * kg + 0]), 0.f);
                v.y = fmaxf(fmaf(a.y, inv, bsh[4 * kg + 1]), 0.f);
                v.z = fmaxf(fmaf(a.z, inv, bsh[4 * kg + 2]), 0.f);
                v.w = fmaxf(fmaf(a.w, inv, bsh[4 * kg + 3]), 0.f);
            }
        }
        int base = (4 * kg) * 260 + row;
        xtf[base]       = v.x;
        xtf[base + 260] = v.y;
        xtf[base + 520] = v.z;
        xtf[base + 780] = v.w;
    }
    __syncthreads();

    // ---- mainloop ----
    const int tx = tid & 7;     // cols 8tx..8tx+7
    const int ty = tid >> 3;    // rows 16ty..16ty+15 (pairs 8ty..8ty+7)
    const ull* xbase = Xt + 8 * ty;
    const float* wbase = Ws + 8 * tx;

    ull acc[8][8];
    #pragma unroll
    for (int i = 0; i < 8; i++)
        #pragma unroll
        for (int j = 0; j < 8; j++) acc[i][j] = 0ull;

    #pragma unroll 2
    for (int k = 0; k < F; k++) {
        float4 wa = *(const float4*)(wbase + k * 64);
        float4 wb = *(const float4*)(wbase + k * 64 + 4);
        ulonglong2 x01 = *(const ulonglong2*)(xbase + k * 130);
        ulonglong2 x23 = *(const ulonglong2*)(xbase + k * 130 + 2);
        ulonglong2 x45 = *(const ulonglong2*)(xbase + k * 130 + 4);
        ulonglong2 x67 = *(const ulonglong2*)(xbase + k * 130 + 6);
        ull wd[8];
        wd[0] = dup2(wa.x); wd[1] = dup2(wa.y); wd[2] = dup2(wa.z); wd[3] = dup2(wa.w);
        wd[4] = dup2(wb.x); wd[5] = dup2(wb.y); wd[6] = dup2(wb.z); wd[7] = dup2(wb.w);
        ull xs[8] = {x01.x, x01.y, x23.x, x23.y, x45.x, x45.y, x67.x, x67.y};
        #pragma unroll
        for (int i = 0; i < 8; i++)
            #pragma unroll
            for (int j = 0; j < 8; j++)
                acc[i][j] = fma2(xs[i], wd[j], acc[i][j]);
    }

    // ---- epilogue: scores, softmax seed, stores ----
    float av[8], dv[8];
    #pragma unroll
    for (int j = 0; j < 8; j++) { av[j] = ash[8 * tx + j]; dv[j] = adsh[8 * tx + j]; }

    float ps[16], pd[16];
    #pragma unroll
    for (int p = 0; p < 8; p++) {
        float lo[8], hi[8];
        #pragma unroll
        for (int j = 0; j < 8; j++) unpack2(acc[p][j], lo[j], hi[j]);
        float s0 = 0.f, d0 = 0.f, s1 = 0.f, d1 = 0.f;
        #pragma unroll
        for (int j = 0; j < 8; j++) {
            s0 += lo[j] * av[j]; d0 += lo[j] * dv[j];
            s1 += hi[j] * av[j]; d1 += hi[j] * dv[j];
        }
        ps[2 * p] = s0; pd[2 * p] = d0; ps[2 * p + 1] = s1; pd[2 * p + 1] = d1;
    }
    #pragma unroll
    for (int off = 1; off < 8; off <<= 1) {
        #pragma unroll
        for (int r = 0; r < 16; r++) {
            ps[r] += __shfl_xor_sync(0xffffffffu, ps[r], off);
            pd[r] += __shfl_xor_sync(0xffffffffu, pd[r], off);
        }
    }

    #pragma unroll
    for (int p = 0; p < 8; p++) {
        int r0 = rowbase + 16 * ty + 2 * p;
        int r1 = r0 + 1;
        float lo[8], hi[8];
        #pragma unroll
        for (int j = 0; j < 8; j++) unpack2(acc[p][j], lo[j], hi[j]);

        float e0 = ps[2 * p] + pd[2 * p];     e0 = e0 > 0.f ? e0 : NEG * e0;
        float e1 = ps[2 * p + 1] + pd[2 * p + 1]; e1 = e1 > 0.f ? e1 : NEG * e1;
        float w0 = __expf(e0);
        float w1 = __expf(e1);

        if (r0 < N_NODES) {
            *(float4*)&hout[(size_t)r0 * F + 8 * tx]     = make_float4(lo[0], lo[1], lo[2], lo[3]);
            *(float4*)&hout[(size_t)r0 * F + 8 * tx + 4] = make_float4(lo[4], lo[5], lo[6], lo[7]);
            *(float4*)&aggout[(size_t)r0 * F + 8 * tx] =
                make_float4(w0 * lo[0], w0 * lo[1], w0 * lo[2], w0 * lo[3]);
            *(float4*)&aggout[(size_t)r0 * F + 8 * tx + 4] =
                make_float4(w0 * lo[4], w0 * lo[5], w0 * lo[6], w0 * lo[7]);
            if (tx == 0) { ssout[r0] = ps[2 * p]; sdout[r0] = pd[2 * p]; denout[r0] = w0; }
        }
        if (r1 < N_NODES) {
            *(float4*)&hout[(size_t)r1 * F + 8 * tx]     = make_float4(hi[0], hi[1], hi[2], hi[3]);
            *(float4*)&hout[(size_t)r1 * F + 8 * tx + 4] = make_float4(hi[4], hi[5], hi[6], hi[7]);
            *(float4*)&aggout[(size_t)r1 * F + 8 * tx] =
                make_float4(w1 * hi[0], w1 * hi[1], w1 * hi[2], w1 * hi[3]);
            *(float4*)&aggout[(size_t)r1 * F + 8 * tx + 4] =
                make_float4(w1 * hi[4], w1 * hi[5], w1 * hi[6], w1 * hi[7]);
            if (tx == 0) { ssout[r1] = ps[2 * p + 1]; sdout[r1] = pd[2 * p + 1]; denout[r1] = w1; }
        }
    }
}

// ---------------- edge scatter, all channels ----------------
__global__ __launch_bounds__(256) void gat_edge_all(const int* __restrict__ EI, int layer)
{
    int gid = blockIdx.x * 256 + threadIdx.x;
    int eg = gid >> 4;
    int j = gid & 15;
    int c = eg / N_EDGES;
    int e = eg - c * N_EDGES;

    const int* src = EI + ((size_t)(c * 2 + layer) * 2) * N_EDGES;
    const int* dst = src + N_EDGES;

    const float* h;
    const float* ss;
    const float* sd;
    float* agg;
    float* den;
    if (layer == 0) { h = g_h1; ss = g_ss1; sd = g_sd1; agg = g_agg; den = g_den1; }
    else            { h = g_h2; ss = g_ss2; sd = g_sd2; agg = g_x2;  den = g_den2; }
    h   += (size_t)c * N_NODES * F;
    agg += (size_t)c * N_NODES * F;
    ss  += (size_t)c * N_NODES;
    sd  += (size_t)c * N_NODES;
    den += (size_t)c * N_NODES;

    int s = __ldg(&src[e]);
    int d = __ldg(&dst[e]);
    float ev = ss[s] + sd[d];
    ev = ev > 0.f ? ev : NEG * ev;
    float w = __expf(ev);

    float4 hv = *(const float4*)&h[(size_t)s * F + 4 * j];
    float* p = &agg[(size_t)d * F + 4 * j];
    asm volatile("red.global.add.v4.f32 [%0], {%1,%2,%3,%4};"
                 :: "l"(p), "f"(w * hv.x), "f"(w * hv.y), "f"(w * hv.z), "f"(w * hv.w)
                 : "memory");
    if (j == 0) atomicAdd(&den[d], w);
}

// ---------------- channel attention combine ----------------
__global__ __launch_bounds__(256) void gat_final(
    const float* __restrict__ b2, const float* __restrict__ att, float* __restrict__ out)
{
    __shared__ float attsh[NCH * F];
    __shared__ float b2sh[NCH * F];
    for (int i = threadIdx.x; i < NCH * F; i += 256) { attsh[i] = att[i]; b2sh[i] = b2[i]; }
    __syncthreads();

    int tid = blockIdx.x * 256 + threadIdx.x;
    int node = tid >> 4;
    int j = tid & 15;
    if (node >= N_NODES) return;

    float4 xs[NCH];
    float sc[NCH];
    #pragma unroll
    for (int c = 0; c < NCH; c++) {
        float inv = 1.f / g_den2[(size_t)c * N_NODES + node];
        float4 v = *(const float4*)&g_x2[((size_t)c * N_NODES + node) * F + 4 * j];
        int cb = c * F + 4 * j;
        v.x = v.x * inv + b2sh[cb + 0];
        v.y = v.y * inv + b2sh[cb + 1];
        v.z = v.z * inv + b2sh[cb + 2];
        v.w = v.w * inv + b2sh[cb + 3];
        xs[c] = v;
        sc[c] = v.x * attsh[cb + 0] + v.y * attsh[cb + 1] + v.z * attsh[cb + 2] + v.w * attsh[cb + 3];
    }
    #pragma unroll
    for (int off = 1; off < 16; off <<= 1) {
        #pragma unroll
        for (int c = 0; c < NCH; c++) sc[c] += __shfl_xor_sync(0xffffffffu, sc[c], off);
    }
    float mx = sc[0];
    #pragma unroll
    for (int c = 1; c < NCH; c++) mx = fmaxf(mx, sc[c]);
    float sum = 0.f;
    float wch[NCH];
    #pragma unroll
    for (int c = 0; c < NCH; c++) { wch[c] = __expf(sc[c] - mx); sum += wch[c]; }
    float inv = 1.f / sum;
    float4 o = make_float4(0.f, 0.f, 0.f, 0.f);
    #pragma unroll
    for (int c = 0; c < NCH; c++) {
        float a = wch[c] * inv;
        o.x += a * xs[c].x; o.y += a * xs[c].y; o.z += a * xs[c].z; o.w += a * xs[c].w;
    }
    *(float4*)&out[(size_t)node * F + 4 * j] = o;
}

// ---------------- launch ----------------
extern "C" void kernel_launch(void* const* d_in, const int* in_sizes, int n_in,
                              void* d_out, int out_size)
{
    const float* emb = (const float*)d_in[0];
    const float* W1  = (const float*)d_in[1];
    const float* as1 = (const float*)d_in[2];
    const float* ad1 = (const float*)d_in[3];
    const float* b1  = (const float*)d_in[4];
    const float* W2  = (const float*)d_in[5];
    const float* as2 = (const float*)d_in[6];
    const float* ad2 = (const float*)d_in[7];
    const float* b2  = (const float*)d_in[8];
    const float* att = (const float*)d_in[9];
    const int*   EI  = (const int*)d_in[10];
    float* out = (float*)d_out;

    const int smem_bytes = 16384 + 64 * 130 * 8 + 3 * F * 4;  // 83712
    cudaFuncSetAttribute(gat_gemm_all, cudaFuncAttributeMaxDynamicSharedMemorySize, smem_bytes);

    const int gemm_grid = NCH * NT;                        // 3519
    const int edge_grid = (NCH * N_EDGES * 16) / 256;      // 281250
    const int fin_grid  = (N_NODES * 16) / 256;            // 6250

    gat_gemm_all<<<gemm_grid, 128, smem_bytes>>>(emb, W1, as1, ad1, b1, 0);
    gat_edge_all<<<edge_grid, 256>>>(EI, 0);
    gat_gemm_all<<<gemm_grid, 128, smem_bytes>>>(emb, W2, as2, ad2, b1, 1);
    gat_edge_all<<<edge_grid, 256>>>(EI, 1);
    gat_final<<<fin_grid, 256>>>(b2, att, out);
}

// round 5
// speedup vs baseline: 1.3143x; 1.1077x over previous
#include <cuda_runtime.h>

#define N_NODES 100000
#define F 64
#define N_EDGES 500000
#define NCH 9
#define NEG 0.2f
#define TILE 256
#define NT ((N_NODES + TILE - 1) / TILE)   // 391
#define M_GROUPS (NCH * N_NODES)           // 900000
#define M_EDGES  (NCH * N_EDGES)           // 4500000
#define NB_SCAN  ((M_GROUPS + 1023) / 1024) // 879

typedef unsigned long long ull;

// ---------------- scratch (device globals; no allocations allowed) ----------
__device__ float g_h1[(size_t)NCH * N_NODES * F];
__device__ float g_h2[(size_t)NCH * N_NODES * F];
__device__ float g_x1[(size_t)NCH * N_NODES * F];   // layer-1 normalized output
__device__ float g_x2[(size_t)NCH * N_NODES * F];   // layer-2 normalized output
__device__ float g_ss1[M_GROUPS];
__device__ float g_sd1[M_GROUPS];
__device__ float g_ws1[M_GROUPS];                   // self-loop weight exp(leaky(ss+sd))
__device__ float g_ss2[M_GROUPS];
__device__ float g_sd2[M_GROUPS];
__device__ float g_ws2[M_GROUPS];
__device__ int   g_cnt[M_GROUPS];
__device__ int   g_off[M_GROUPS];
__device__ int   g_cur[M_GROUPS];
__device__ int   g_bsum[1024];
__device__ int   g_boff[1024];
__device__ int   g_csrc[M_EDGES];

// ---------------- f32x2 helpers ----------------
__device__ __forceinline__ ull fma2(ull a, ull b, ull c) {
    ull d;
    asm("fma.rn.f32x2 %0, %1, %2, %3;" : "=l"(d) : "l"(a), "l"(b), "l"(c));
    return d;
}
__device__ __forceinline__ ull dup2(float x) {
    ull r;
    asm("mov.b64 %0, {%1, %1};" : "=l"(r) : "f"(x));
    return r;
}
__device__ __forceinline__ void unpack2(ull v, float& lo, float& hi) {
    asm("mov.b64 {%0, %1}, %2;" : "=f"(lo), "=f"(hi) : "l"(v));
}

// ---------------- fused GEMM + scores + self-loop weight, all channels -----
// 256 threads, one (channel, 256-row) tile. Micro-tile 8 rows x 8 cols.
// layer==1: X = relu(g_x1 + b1) computed on the fly.
__global__ __launch_bounds__(256, 2) void gat_gemm_all(
    const float* __restrict__ Xg,
    const float* __restrict__ Wall,
    const float* __restrict__ asall,
    const float* __restrict__ adall,
    const float* __restrict__ bprevall,
    int layer)
{
    extern __shared__ char smem[];
    float* Ws = (float*)smem;                              // [64][64] scalar, 16KB
    ull*   Xt = (ull*)(smem + 16384);                      // [64][130] row-pairs
    float* ash  = (float*)(smem + 16384 + 64 * 130 * 8);
    float* adsh = ash + F;
    float* bsh  = adsh + F;

    const int bx = blockIdx.x;
    const int c = bx / NT;
    const int tile = bx % NT;
    const int tid = threadIdx.x;
    const int rowbase = tile * TILE;

    const float* W = Wall + (size_t)c * F * F;
    for (int i = tid; i < F * F / 4; i += 256)
        ((float4*)Ws)[i] = ((const float4*)W)[i];
    if (tid < F) {
        ash[tid]  = asall[c * F + tid];
        adsh[tid] = adall[c * F + tid];
        bsh[tid]  = layer ? bprevall[c * F + tid] : 0.f;
    }
    __syncthreads();   // bsh read by Xt fill below (layer 1)

    const float* xin = g_x1 + (size_t)c * N_NODES * F;
    float* hout  = (layer ? g_h2 : g_h1) + (size_t)c * N_NODES * F;
    float* ssout = (layer ? g_ss2 : g_ss1) + (size_t)c * N_NODES;
    float* sdout = (layer ? g_sd2 : g_sd1) + (size_t)c * N_NODES;
    float* wsout = (layer ? g_ws2 : g_ws1) + (size_t)c * N_NODES;

    // ---- fill Xt: transpose 256 rows x 64 cols to k-major (float idx k*260+row)
    float* xtf = (float*)Xt;
    #pragma unroll
    for (int it = 0; it < 16; it++) {
        int lin = it * 256 + tid;          // 0..4095 float4s
        int kg = lin >> 8;                 // 0..15 (4 k each)
        int row = lin & 255;
        int gr = rowbase + row;
        float4 v = make_float4(0.f, 0.f, 0.f, 0.f);
        if (gr < N_NODES) {
            if (layer == 0) {
                v = *(const float4*)&Xg[(size_t)gr * F + 4 * kg];
            } else {
                float4 a = *(const float4*)&xin[(size_t)gr * F + 4 * kg];
                v.x = fmaxf(a.x + bsh[4 * kg + 0], 0.f);
                v.y = fmaxf(a.y + bsh[4 * kg + 1], 0.f);
                v.z = fmaxf(a.z + bsh[4 * kg + 2], 0.f);
                v.w = fmaxf(a.w + bsh[4 * kg + 3], 0.f);
            }
        }
        int base = (4 * kg) * 260 + row;
        xtf[base]       = v.x;
        xtf[base + 260] = v.y;
        xtf[base + 520] = v.z;
        xtf[base + 780] = v.w;
    }
    __syncthreads();

    // ---- mainloop: 8 rows (4 pairs) x 8 cols per thread ----
    const int tx = tid & 7;     // cols 8tx..8tx+7
    const int ty = tid >> 3;    // 0..31 ; rows 8ty..8ty+7 (pairs 4ty..4ty+3)
    const ull* xbase = Xt + 4 * ty;
    const float* wbase = Ws + 8 * tx;

    ull acc[4][8];
    #pragma unroll
    for (int i = 0; i < 4; i++)
        #pragma unroll
        for (int j = 0; j < 8; j++) acc[i][j] = 0ull;

    #pragma unroll 4
    for (int k = 0; k < F; k++) {
        float4 wa = *(const float4*)(wbase + k * 64);
        float4 wb = *(const float4*)(wbase + k * 64 + 4);
        ulonglong2 x01 = *(const ulonglong2*)(xbase + k * 130);
        ulonglong2 x23 = *(const ulonglong2*)(xbase + k * 130 + 2);
        ull wd[8];
        wd[0] = dup2(wa.x); wd[1] = dup2(wa.y); wd[2] = dup2(wa.z); wd[3] = dup2(wa.w);
        wd[4] = dup2(wb.x); wd[5] = dup2(wb.y); wd[6] = dup2(wb.z); wd[7] = dup2(wb.w);
        ull xs[4] = {x01.x, x01.y, x23.x, x23.y};
        #pragma unroll
        for (int i = 0; i < 4; i++)
            #pragma unroll
            for (int j = 0; j < 8; j++)
                acc[i][j] = fma2(xs[i], wd[j], acc[i][j]);
    }

    // ---- epilogue ----
    float av[8], dv[8];
    #pragma unroll
    for (int j = 0; j < 8; j++) { av[j] = ash[8 * tx + j]; dv[j] = adsh[8 * tx + j]; }

    float ps[8], pd[8];
    #pragma unroll
    for (int p = 0; p < 4; p++) {
        float lo[8], hi[8];
        #pragma unroll
        for (int j = 0; j < 8; j++) unpack2(acc[p][j], lo[j], hi[j]);
        float s0 = 0.f, d0 = 0.f, s1 = 0.f, d1 = 0.f;
        #pragma unroll
        for (int j = 0; j < 8; j++) {
            s0 += lo[j] * av[j]; d0 += lo[j] * dv[j];
            s1 += hi[j] * av[j]; d1 += hi[j] * dv[j];
        }
        ps[2 * p] = s0; pd[2 * p] = d0; ps[2 * p + 1] = s1; pd[2 * p + 1] = d1;
    }
    #pragma unroll
    for (int off = 1; off < 8; off <<= 1) {
        #pragma unroll
        for (int r = 0; r < 8; r++) {
            ps[r] += __shfl_xor_sync(0xffffffffu, ps[r], off);
            pd[r] += __shfl_xor_sync(0xffffffffu, pd[r], off);
        }
    }

    #pragma unroll
    for (int p = 0; p < 4; p++) {
        int r0 = rowbase + 8 * ty + 2 * p;
        int r1 = r0 + 1;
        float lo[8], hi[8];
        #pragma unroll
        for (int j = 0; j < 8; j++) unpack2(acc[p][j], lo[j], hi[j]);

        if (r0 < N_NODES) {
            *(float4*)&hout[(size_t)r0 * F + 8 * tx]     = make_float4(lo[0], lo[1], lo[2], lo[3]);
            *(float4*)&hout[(size_t)r0 * F + 8 * tx + 4] = make_float4(lo[4], lo[5], lo[6], lo[7]);
            if (tx == 0) {
                float e = ps[2 * p] + pd[2 * p]; e = e > 0.f ? e : NEG * e;
                ssout[r0] = ps[2 * p]; sdout[r0] = pd[2 * p]; wsout[r0] = __expf(e);
            }
        }
        if (r1 < N_NODES) {
            *(float4*)&hout[(size_t)r1 * F + 8 * tx]     = make_float4(hi[0], hi[1], hi[2], hi[3]);
            *(float4*)&hout[(size_t)r1 * F + 8 * tx + 4] = make_float4(hi[4], hi[5], hi[6], hi[7]);
            if (tx == 0) {
                float e = ps[2 * p + 1] + pd[2 * p + 1]; e = e > 0.f ? e : NEG * e;
                ssout[r1] = ps[2 * p + 1]; sdout[r1] = pd[2 * p + 1]; wsout[r1] = __expf(e);
            }
        }
    }
}

// ---------------- CSR build ----------------
__global__ __launch_bounds__(256) void k_zero()
{
    int i = blockIdx.x * 256 + threadIdx.x;
    if (i < M_GROUPS) g_cnt[i] = 0;
}

__global__ __launch_bounds__(256) void k_count(const int* __restrict__ EI, int layer)
{
    int t = blockIdx.x * 256 + threadIdx.x;
    if (t >= M_EDGES) return;
    int c = t / N_EDGES;
    int e = t - c * N_EDGES;
    int d = EI[((size_t)(c * 2 + layer) * 2 + 1) * N_EDGES + e];
    atomicAdd(&g_cnt[c * N_NODES + d], 1);
}

__global__ __launch_bounds__(256) void k_scan1()
{
    __shared__ int sh[256];
    int tid = threadIdx.x;
    int base = blockIdx.x * 1024 + tid * 4;
    int v0 = 0, v1 = 0, v2 = 0, v3 = 0;
    if (base + 3 < M_GROUPS) {
        int4 t = *(const int4*)&g_cnt[base];
        v0 = t.x; v1 = t.y; v2 = t.z; v3 = t.w;
    } else {
        if (base     < M_GROUPS) v0 = g_cnt[base];
        if (base + 1 < M_GROUPS) v1 = g_cnt[base + 1];
        if (base + 2 < M_GROUPS) v2 = g_cnt[base + 2];
        if (base + 3 < M_GROUPS) v3 = g_cnt[base + 3];
    }
    int tsum = v0 + v1 + v2 + v3;
    sh[tid] = tsum;
    __syncthreads();
    for (int off = 1; off < 256; off <<= 1) {
        int t = (tid >= off) ? sh[tid - off] : 0;
        __syncthreads();
        sh[tid] += t;
        __syncthreads();
    }
    int excl = sh[tid] - tsum;
    if (base     < M_GROUPS) g_off[base]     = excl;
    if (base + 1 < M_GROUPS) g_off[base + 1] = excl + v0;
    if (base + 2 < M_GROUPS) g_off[base + 2] = excl + v0 + v1;
    if (base + 3 < M_GROUPS) g_off[base + 3] = excl + v0 + v1 + v2;
    if (tid == 255) g_bsum[blockIdx.x] = sh[255];
}

__global__ __launch_bounds__(1024) void k_scan2()
{
    __shared__ int sh[1024];
    int tid = threadIdx.x;
    int v = (tid < NB_SCAN) ? g_bsum[tid] : 0;
    sh[tid] = v;
    __syncthreads();
    for (int off = 1; off < 1024; off <<= 1) {
        int t = (tid >= off) ? sh[tid - off] : 0;
        __syncthreads();
        sh[tid] += t;
        __syncthreads();
    }
    if (tid < NB_SCAN) g_boff[tid] = sh[tid] - v;
}

__global__ __launch_bounds__(256) void k_scan3()
{
    int i = blockIdx.x * 256 + threadIdx.x;
    if (i >= M_GROUPS) return;
    int v = g_off[i] + g_boff[i >> 10];
    g_off[i] = v;
    g_cur[i] = v;
}

__global__ __launch_bounds__(256) void k_scatter(const int* __restrict__ EI, int layer)
{
    int t = blockIdx.x * 256 + threadIdx.x;
    if (t >= M_EDGES) return;
    int c = t / N_EDGES;
    int e = t - c * N_EDGES;
    const int* src = EI + ((size_t)(c * 2 + layer) * 2) * N_EDGES;
    const int* dst = src + N_EDGES;
    int s = src[e];
    int d = dst[e];
    int pos = atomicAdd(&g_cur[c * N_NODES + d], 1);
    g_csrc[pos] = s;
}

// ---------------- gather aggregation: x = (w_self*h[n] + sum w*h[s]) / den --
__global__ __launch_bounds__(256) void gat_aggregate(int layer)
{
    int gid = blockIdx.x * 256 + threadIdx.x;
    int g = gid >> 4;
    int j = gid & 15;
    if (g >= M_GROUPS) return;
    int c = g / N_NODES;
    int node = g - c * N_NODES;

    const float* h  = (layer ? g_h2 : g_h1) + (size_t)c * N_NODES * F;
    const float* ss = (layer ? g_ss2 : g_ss1) + (size_t)c * N_NODES;
    float sdn   = (layer ? g_sd2 : g_sd1)[g];
    float wself = (layer ? g_ws2 : g_ws1)[g];
    float* xout = (layer ? g_x2 : g_x1) + (size_t)c * N_NODES * F;

    float4 hv = *(const float4*)&h[(size_t)node * F + 4 * j];
    float4 acc = make_float4(wself * hv.x, wself * hv.y, wself * hv.z, wself * hv.w);
    float den = wself;

    int start = g_off[g];
    int end = (g == M_GROUPS - 1) ? M_EDGES : g_off[g + 1];
    for (int i = start; i < end; i++) {
        int s = __ldg(&g_csrc[i]);
        float e = __ldg(&ss[s]) + sdn;
        e = e > 0.f ? e : NEG * e;
        float w = __expf(e);
        float4 v = *(const float4*)&h[(size_t)s * F + 4 * j];
        acc.x += w * v.x; acc.y += w * v.y; acc.z += w * v.z; acc.w += w * v.w;
        den += w;
    }
    float inv = 1.f / den;
    *(float4*)&xout[(size_t)node * F + 4 * j] =
        make_float4(acc.x * inv, acc.y * inv, acc.z * inv, acc.w * inv);
}

// ---------------- channel attention combine (x2 already normalized) --------
__global__ __launch_bounds__(256) void gat_final(
    const float* __restrict__ b2, const float* __restrict__ att, float* __restrict__ out)
{
    __shared__ float attsh[NCH * F];
    __shared__ float b2sh[NCH * F];
    for (int i = threadIdx.x; i < NCH * F; i += 256) { attsh[i] = att[i]; b2sh[i] = b2[i]; }
    __syncthreads();

    int tid = blockIdx.x * 256 + threadIdx.x;
    int node = tid >> 4;
    int j = tid & 15;
    if (node >= N_NODES) return;

    float4 xs[NCH];
    float sc[NCH];
    #pragma unroll
    for (int c = 0; c < NCH; c++) {
        float4 v = *(const float4*)&g_x2[((size_t)c * N_NODES + node) * F + 4 * j];
        int cb = c * F + 4 * j;
        v.x += b2sh[cb + 0];
        v.y += b2sh[cb + 1];
        v.z += b2sh[cb + 2];
        v.w += b2sh[cb + 3];
        xs[c] = v;
        sc[c] = v.x * attsh[cb + 0] + v.y * attsh[cb + 1] + v.z * attsh[cb + 2] + v.w * attsh[cb + 3];
    }
    #pragma unroll
    for (int off = 1; off < 16; off <<= 1) {
        #pragma unroll
        for (int c = 0; c < NCH; c++) sc[c] += __shfl_xor_sync(0xffffffffu, sc[c], off);
    }
    float mx = sc[0];
    #pragma unroll
    for (int c = 1; c < NCH; c++) mx = fmaxf(mx, sc[c]);
    float sum = 0.f;
    float wch[NCH];
    #pragma unroll
    for (int c = 0; c < NCH; c++) { wch[c] = __expf(sc[c] - mx); sum += wch[c]; }
    float inv = 1.f / sum;
    float4 o = make_float4(0.f, 0.f, 0.f, 0.f);
    #pragma unroll
    for (int c = 0; c < NCH; c++) {
        float a = wch[c] * inv;
        o.x += a * xs[c].x; o.y += a * xs[c].y; o.z += a * xs[c].z; o.w += a * xs[c].w;
    }
    *(float4*)&out[(size_t)node * F + 4 * j] = o;
}

// ---------------- launch ----------------
extern "C" void kernel_launch(void* const* d_in, const int* in_sizes, int n_in,
                              void* d_out, int out_size)
{
    const float* emb = (const float*)d_in[0];
    const float* W1  = (const float*)d_in[1];
    const float* as1 = (const float*)d_in[2];
    const float* ad1 = (const float*)d_in[3];
    const float* b1  = (const float*)d_in[4];
    const float* W2  = (const float*)d_in[5];
    const float* as2 = (const float*)d_in[6];
    const float* ad2 = (const float*)d_in[7];
    const float* b2  = (const float*)d_in[8];
    const float* att = (const float*)d_in[9];
    const int*   EI  = (const int*)d_in[10];
    float* out = (float*)d_out;

    const int smem_bytes = 16384 + 64 * 130 * 8 + 3 * F * 4;  // 83712
    cudaFuncSetAttribute(gat_gemm_all, cudaFuncAttributeMaxDynamicSharedMemorySize, smem_bytes);

    const int gemm_grid  = NCH * NT;                       // 3519
    const int grp_grid   = (M_GROUPS + 255) / 256;         // 3516
    const int edge_grid  = (M_EDGES + 255) / 256;          // 17579
    const int agg_grid   = (M_GROUPS * 16 + 255) / 256;    // 56250
    const int fin_grid   = (N_NODES * 16) / 256;           // 6250

    for (int layer = 0; layer < 2; layer++) {
        gat_gemm_all<<<gemm_grid, 256, smem_bytes>>>(
            emb, layer ? W2 : W1, layer ? as2 : as1, layer ? ad2 : ad1, b1, layer);
        k_zero<<<grp_grid, 256>>>();
        k_count<<<edge_grid, 256>>>(EI, layer);
        k_scan1<<<NB_SCAN, 256>>>();
        k_scan2<<<1, 1024>>>();
        k_scan3<<<grp_grid, 256>>>();
        k_scatter<<<edge_grid, 256>>>(EI, layer);
        gat_aggregate<<<agg_grid, 256>>>(layer);
    }
    gat_final<<<fin_grid, 256>>>(b2, att, out);
}